// round 16
// baseline (speedup 1.0000x reference)
#include <cuda_runtime.h>
#include <cuda_fp16.h>
#include <math_constants.h>
#include <cstdint>

#define NUM_HEADS 8
#define TOPK 4
#define D_MODEL 128
#define CH 16
#define P2 64
#define W2 256
#define NVIEW 2
#define SCALE_LOG2E ((float)(0.08838834764831845 * 1.4426950408889634))
#define KST 24   // kv_s row stride (halves): word=row*12+q4 -> 32 distinct banks
#define VST 72   // vt_s row stride (halves): word=(4lr+q4) mod 32 -> conflict-free

__device__ float g_qwin[P2 * D_MODEL];
__device__ float g_kwinT[D_MODEL * NVIEW * P2];   // [channel][view*win] transposed
__device__ int   g_ridx[P2 * TOPK];

// pack two f32 -> half2 -> 2^x
__device__ __forceinline__ uint32_t p_ex2(float lo, float hi) {
    uint32_t r;
    asm("{\n\t.reg .b32 t;\n\t"
        "cvt.rn.f16x2.f32 t, %2, %1;\n\t"
        "ex2.approx.f16x2 %0, t;\n\t}"
        : "=r"(r) : "f"(lo), "f"(hi));
    return r;
}

__device__ __forceinline__ void mma_f16(float d[4], const uint32_t a[4],
                                        uint32_t b0, uint32_t b1, const float c[4]) {
    asm volatile(
        "mma.sync.aligned.m16n8k16.row.col.f32.f16.f16.f32 "
        "{%0,%1,%2,%3}, {%4,%5,%6,%7}, {%8,%9}, {%10,%11,%12,%13};"
        : "=f"(d[0]), "=f"(d[1]), "=f"(d[2]), "=f"(d[3])
        : "r"(a[0]), "r"(a[1]), "r"(a[2]), "r"(a[3]), "r"(b0), "r"(b1),
          "f"(c[0]), "f"(c[1]), "f"(c[2]), "f"(c[3]));
}

// ---------------------------------------------------------------------------
// Kernel 1: window means. CHANGE: 512 threads (all 192 blocks co-resident in
// one wave), 16 float4 loads per thread (deeper MLP). k output TRANSPOSED.
// ---------------------------------------------------------------------------
__global__ void win_mean_kernel(const float* __restrict__ cv,
                                const float* __restrict__ mv) {
    __shared__ float4 red[512];
    int b = blockIdx.x;
    int t = threadIdx.x;
    int c4 = t & 31;           // float4 index over 128 channels
    int part = t >> 5;         // 16 parts x 16 pixels
    const float* src;
    int p;
    bool is_q = (b < P2);
    int widx = 0;
    if (is_q) {
        p = b; src = cv;
    } else {
        int vp = b - P2;
        int v = vp >> 6; p = vp & 63;
        src = mv + (size_t)v * 128 * 128 * 128;
        widx = vp;
    }
    int jp = p >> 3, ip = p & 7;
    int y0 = jp * 16, x0 = ip * 16;
    float4 s = make_float4(0.f, 0.f, 0.f, 0.f);
    #pragma unroll
    for (int u = 0; u < 16; u++) {
        int pix = part * 16 + u;
        int hh = pix >> 4, ww = pix & 15;
        float4 x = *(reinterpret_cast<const float4*>(
            src + ((size_t)(y0 + hh) * 128 + (x0 + ww)) * 128) + c4);
        s.x += x.x; s.y += x.y; s.z += x.z; s.w += x.w;
    }
    red[t] = s;
    __syncthreads();
    if (t < 32) {
        float4 acc = make_float4(0.f, 0.f, 0.f, 0.f);
        #pragma unroll
        for (int k = 0; k < 16; k++) {
            float4 x = red[k * 32 + t];
            acc.x += x.x; acc.y += x.y; acc.z += x.z; acc.w += x.w;
        }
        const float inv = 1.f / 256.f;
        acc.x *= inv; acc.y *= inv; acc.z *= inv; acc.w *= inv;
        if (is_q) {
            reinterpret_cast<float4*>(g_qwin + p * D_MODEL)[t] = acc;
        } else {
            g_kwinT[(4 * t + 0) * 128 + widx] = acc.x;
            g_kwinT[(4 * t + 1) * 128 + widx] = acc.y;
            g_kwinT[(4 * t + 2) * 128 + widx] = acc.z;
            g_kwinT[(4 * t + 3) * 128 + widx] = acc.w;
        }
    }
}

// ---------------------------------------------------------------------------
// Kernel 2: routing + top-4, coalesced kT. (validated, unchanged)
// ---------------------------------------------------------------------------
__global__ void topk_kernel() {
    __shared__ float q_s[D_MODEL];
    __shared__ float logit[128];
    int row = blockIdx.x;
    int t = threadIdx.x;

    q_s[t] = g_qwin[row * D_MODEL + t];
    __syncthreads();

    float s = 0.f;
    #pragma unroll 16
    for (int c = 0; c < D_MODEL; c++)
        s += q_s[c] * g_kwinT[c * 128 + t];
    logit[t] = s;
    __syncthreads();

    if (t < 32) {
        float v[4]; int id[4];
        #pragma unroll
        for (int kloc = 0; kloc < 4; kloc++) {
            int j = t * 4 + kloc;
            v[kloc] = logit[j]; id[kloc] = j;
        }
        #pragma unroll
        for (int r = 0; r < TOPK; r++) {
            float bv = v[0]; int bi = id[0];
            #pragma unroll
            for (int kloc = 1; kloc < 4; kloc++)
                if (v[kloc] > bv || (v[kloc] == bv && id[kloc] < bi)) { bv = v[kloc]; bi = id[kloc]; }
            float wv = bv; int wi = bi;
            #pragma unroll
            for (int off = 16; off; off >>= 1) {
                float ov = __shfl_down_sync(0xffffffffu, wv, off);
                int   oi = __shfl_down_sync(0xffffffffu, wi, off);
                if (ov > wv || (ov == wv && oi < wi)) { wv = ov; wi = oi; }
            }
            wi = __shfl_sync(0xffffffffu, wi, 0);
            if ((wi >> 2) == t) v[wi & 3] = -CUDART_INF_F;
            if (t == 0) g_ridx[row * TOPK + r] = wi;
        }
    }
}

// ---------------------------------------------------------------------------
// Kernel 3: fp16 attention. (validated r15 structure, unchanged)
// 8 outer chunks of 128 kv rows, two 64-row interleaved-mt passes per
// barrier. Grid (64,8), 256 threads / 8 warps x 32 q-rows, occ 2.
// ---------------------------------------------------------------------------
__global__ void __launch_bounds__(256, 2)
attn_kernel(const float* __restrict__ cv,
            const float* __restrict__ mv,
            float* __restrict__ out) {
    int p = blockIdx.x;      // window
    int m = blockIdx.y;      // head
    int t = threadIdx.x;
    int warp = t >> 5, lane = t & 31;
    int lr = lane >> 2, q4 = lane & 3;

    __shared__ __half q_s[W2 * CH];           // 8 KB
    __shared__ __half kv_s[2][128 * KST];     // 2 x 6 KB (k-major, padded)
    __shared__ __half vt_s[2][2][CH * VST];   // 2 buf x 2 sub x 2.25 KB
    __shared__ int sel_s[TOPK];

    int jp = p >> 3, ip = p & 7;

    // ---- stage Q: all 256 pixels ----
    {
        int hh = t >> 4, ww = t & 15;
        const float4* gp = reinterpret_cast<const float4*>(
            cv + ((size_t)(jp * 16 + hh) * 128 + (ip * 16 + ww)) * 128 + m * CH);
        float4 x0 = gp[0], x1 = gp[1], x2 = gp[2], x3 = gp[3];
        const float s = SCALE_LOG2E;
        __half2* dst = reinterpret_cast<__half2*>(q_s + t * CH);
        dst[0] = __floats2half2_rn(x0.x * s, x0.y * s);
        dst[1] = __floats2half2_rn(x0.z * s, x0.w * s);
        dst[2] = __floats2half2_rn(x1.x * s, x1.y * s);
        dst[3] = __floats2half2_rn(x1.z * s, x1.w * s);
        dst[4] = __floats2half2_rn(x2.x * s, x2.y * s);
        dst[5] = __floats2half2_rn(x2.z * s, x2.w * s);
        dst[6] = __floats2half2_rn(x3.x * s, x3.y * s);
        dst[7] = __floats2half2_rn(x3.z * s, x3.w * s);
    }
    if (t < TOPK) sel_s[t] = g_ridx[p * TOPK + t];
    __syncthreads();

    int sel[TOPK];
    #pragma unroll
    for (int k = 0; k < TOPK; k++) sel[k] = sel_s[k];

    // ---- Q a-frags: two m16 tiles per warp ----
    uint32_t qa[2][4];
    #pragma unroll
    for (int mt = 0; mt < 2; mt++) {
        int r0 = warp * 32 + mt * 16 + lr;
        qa[mt][0] = *reinterpret_cast<const uint32_t*>(q_s + r0 * CH + 2 * q4);
        qa[mt][1] = *reinterpret_cast<const uint32_t*>(q_s + (r0 + 8) * CH + 2 * q4);
        qa[mt][2] = *reinterpret_cast<const uint32_t*>(q_s + r0 * CH + 8 + 2 * q4);
        qa[mt][3] = *reinterpret_cast<const uint32_t*>(q_s + (r0 + 8) * CH + 8 + 2 * q4);
    }

    // staging roles: 256 threads = 32 pixel-slots x 8 ch-pairs; 4 pixels each
    int pixg = t >> 3;
    int cg   = t & 7;

    float o[2][2][4];      // [mtile][nc][4]
    float ls[2][2];        // [mtile][half]
    #pragma unroll
    for (int mt = 0; mt < 2; mt++) {
        ls[mt][0] = 0.f; ls[mt][1] = 0.f;
        #pragma unroll
        for (int u = 0; u < 4; u++) { o[mt][0][u] = 0.f; o[mt][1][u] = 0.f; }
    }

    // outer chunk c: kv rows [c*128, c*128+128) = window sel[c>>1], off (c&1)*128
    auto ldchunk = [&](int c, float2 f[4]) {
        int s = sel[c >> 1];
        int jv = (s & 63) >> 3, iv = s & 7;
        const float* base = mv + (size_t)(s >> 6) * 128 * 128 * 128;
        int goff = (c & 1) * 128;
        #pragma unroll
        for (int k = 0; k < 4; k++) {
            int pixl = goff + pixg + 32 * k;
            int yy = jv * 16 + (pixl >> 4), xx = iv * 16 + (pixl & 15);
            f[k] = *reinterpret_cast<const float2*>(
                base + ((size_t)yy * 128 + xx) * 128 + m * CH + cg * 2);
        }
    };
    auto stchunk = [&](int buf, const float2 f[4]) {
        #pragma unroll
        for (int k = 0; k < 4; k++) {
            int pix = pixg + 32 * k;
            __half2 h = __floats2half2_rn(f[k].x, f[k].y);
            *reinterpret_cast<__half2*>(kv_s[buf] + pix * KST + cg * 2) = h;
            __half* vt = vt_s[buf][k >> 1];
            int col = pix & 63;
            vt[(cg * 2) * VST + col]     = __low2half(h);
            vt[(cg * 2 + 1) * VST + col] = __high2half(h);
        }
    };

    {
        float2 f[4];
        ldchunk(0, f);
        stchunk(0, f);
    }
    __syncthreads();

    for (int c = 0; c < 8; c++) {
        int cur = c & 1;
        float2 nf[4];
        if (c + 1 < 8) ldchunk(c + 1, nf);   // LDG hides under TWO passes

        #pragma unroll
        for (int j = 0; j < 2; j++) {
            // ---- S = Q K^T for BOTH tiles over shared K b-frags ----
            uint32_t pa[2][4][4];
            #pragma unroll
            for (int g = 0; g < 2; g++) {
                float sc0[4][4], sc1[4][4];
                #pragma unroll
                for (int nt = 0; nt < 4; nt++)
                    #pragma unroll
                    for (int u = 0; u < 4; u++) { sc0[nt][u] = 0.f; sc1[nt][u] = 0.f; }
                #pragma unroll
                for (int nt = 0; nt < 4; nt++) {
                    int row = j * 64 + (g * 4 + nt) * 8 + lr;
                    const __half* kr = kv_s[cur] + row * KST;
                    uint32_t b0 = *reinterpret_cast<const uint32_t*>(kr + 2 * q4);
                    uint32_t b1 = *reinterpret_cast<const uint32_t*>(kr + 8 + 2 * q4);
                    mma_f16(sc0[nt], qa[0], b0, b1, sc0[nt]);
                    mma_f16(sc1[nt], qa[1], b0, b1, sc1[nt]);
                }
                #pragma unroll
                for (int ks = 0; ks < 2; ks++) {
                    int kg = g * 2 + ks;
                    pa[0][kg][0] = p_ex2(sc0[2 * ks][0],     sc0[2 * ks][1]);
                    pa[0][kg][1] = p_ex2(sc0[2 * ks][2],     sc0[2 * ks][3]);
                    pa[0][kg][2] = p_ex2(sc0[2 * ks + 1][0], sc0[2 * ks + 1][1]);
                    pa[0][kg][3] = p_ex2(sc0[2 * ks + 1][2], sc0[2 * ks + 1][3]);
                    pa[1][kg][0] = p_ex2(sc1[2 * ks][0],     sc1[2 * ks][1]);
                    pa[1][kg][1] = p_ex2(sc1[2 * ks][2],     sc1[2 * ks][3]);
                    pa[1][kg][2] = p_ex2(sc1[2 * ks + 1][0], sc1[2 * ks + 1][1]);
                    pa[1][kg][3] = p_ex2(sc1[2 * ks + 1][2], sc1[2 * ks + 1][3]);
                }
            }

            // ---- O += P V for BOTH tiles over shared V b-frags ----
            #pragma unroll
            for (int ks = 0; ks < 4; ks++) {
                #pragma unroll
                for (int nc = 0; nc < 2; nc++) {
                    const __half* vr = vt_s[cur][j] + (nc * 8 + lr) * VST + ks * 16;
                    uint32_t b0 = *reinterpret_cast<const uint32_t*>(vr + 2 * q4);
                    uint32_t b1 = *reinterpret_cast<const uint32_t*>(vr + 8 + 2 * q4);
                    mma_f16(o[0][nc], pa[0][ks], b0, b1, o[0][nc]);
                    mma_f16(o[1][nc], pa[1][ks], b0, b1, o[1][nc]);
                }
            }

            // ---- row sums on scalar pipes (fills tensor-drain window) ----
            #pragma unroll
            for (int mt = 0; mt < 2; mt++) {
                #pragma unroll
                for (int ks = 0; ks < 4; ks++) {
                    __half2 w0 = __hadd2(*reinterpret_cast<__half2*>(&pa[mt][ks][0]),
                                         *reinterpret_cast<__half2*>(&pa[mt][ks][2]));
                    __half2 w1 = __hadd2(*reinterpret_cast<__half2*>(&pa[mt][ks][1]),
                                         *reinterpret_cast<__half2*>(&pa[mt][ks][3]));
                    float2 f0 = __half22float2(w0);
                    float2 f1 = __half22float2(w1);
                    ls[mt][0] += f0.x + f0.y;
                    ls[mt][1] += f1.x + f1.y;
                }
            }
        }

        if (c + 1 < 8) stchunk(cur ^ 1, nf);
        __syncthreads();
    }

    // ---- epilogue: quad-reduce row sums, normalize, store ----
    #pragma unroll
    for (int mt = 0; mt < 2; mt++) {
        #pragma unroll
        for (int h = 0; h < 2; h++) {
            float lt = ls[mt][h];
            lt += __shfl_xor_sync(0xffffffffu, lt, 1);
            lt += __shfl_xor_sync(0xffffffffu, lt, 2);
            float inv = 1.f / lt;
            int pix = warp * 32 + mt * 16 + h * 8 + lr;
            int hh = pix >> 4, ww = pix & 15;
            float* op = out + ((size_t)(jp * 16 + hh) * 128 + (ip * 16 + ww)) * 128 + m * CH;
            #pragma unroll
            for (int nc = 0; nc < 2; nc++) {
                float2 st;
                st.x = o[mt][nc][2 * h]     * inv;
                st.y = o[mt][nc][2 * h + 1] * inv;
                *reinterpret_cast<float2*>(op + nc * 8 + 2 * q4) = st;
            }
        }
    }
}

extern "C" void kernel_launch(void* const* d_in, const int* in_sizes, int n_in,
                              void* d_out, int out_size) {
    const float* cv = (const float*)d_in[0];   // (1,128,128,128)
    const float* mv = (const float*)d_in[1];   // (1,2,128,128,128)
    float* out = (float*)d_out;                // (1,128,128,128)

    win_mean_kernel<<<192, 512>>>(cv, mv);
    topk_kernel<<<64, 128>>>();
    dim3 grid(P2, NUM_HEADS);
    attn_kernel<<<grid, 256>>>(cv, mv, out);
}